// round 16
// baseline (speedup 1.0000x reference)
#include <cuda_runtime.h>
#include <math.h>

#define N_TOK 1024
#define TOPK  2
#define NE    16
#define NH    1024
#define ND    2048
#define NR    16
#define NS    (N_TOK*TOPK)
#define LSCALE 0.25f

typedef unsigned long long u64;

// ---- packed f32x2 helpers (sm_100+ PTX; FFMA2 is PTX-only per SASS_QUICKREF) ----
__device__ __forceinline__ u64 pk2(float x, float y){
    u64 r; asm("mov.b64 %0,{%1,%2};" : "=l"(r) : "f"(x), "f"(y)); return r;
}
__device__ __forceinline__ void upk2(u64 v, float& x, float& y){
    asm("mov.b64 {%0,%1},%2;" : "=f"(x), "=f"(y) : "l"(v));
}
__device__ __forceinline__ u64 f2fma(u64 a, u64 b, u64 c){
    u64 d; asm("fma.rn.f32x2 %0,%1,%2,%3;" : "=l"(d) : "l"(a), "l"(b), "l"(c)); return d;
}

// ---- scratch (static device globals: allocation-free) ----
__device__ int   g_perm[NS];
__device__ int   g_off[NE + 1];
__device__ float g_tup[NS * NR];
__device__ float g_tdn[NS * NR];
__device__ float g_act[(size_t)NS * NH];   // 8 MB

// ============================================================
// Kernel: zero output (harness poisons d_out)
// ============================================================
__global__ void k_zero(float* __restrict__ out){
    int i = blockIdx.x * blockDim.x + threadIdx.x;
    float4 z = {0.f, 0.f, 0.f, 0.f};
    if (i < (N_TOK * ND) / 4) ((float4*)out)[i] = z;
}

// ============================================================
// Kernel: counting sort of slots by expert (1 block)
// ============================================================
__global__ void k_sort(const int* __restrict__ ids){
    __shared__ int cnt[NE], cur[NE];
    int t = threadIdx.x;
    if (t < NE) cnt[t] = 0;
    __syncthreads();
    for (int s = t; s < NS; s += blockDim.x) atomicAdd(&cnt[ids[s]], 1);
    __syncthreads();
    if (t == 0){
        int acc = 0;
        for (int e = 0; e < NE; e++){ g_off[e] = acc; cur[e] = acc; acc += cnt[e]; }
        g_off[NE] = acc;
    }
    __syncthreads();
    for (int s = t; s < NS; s += blockDim.x){
        int e = ids[s];
        int p = atomicAdd(&cur[e], 1);
        g_perm[p] = s;
    }
}

// ============================================================
// Kernel: t_up[p][r] = sum_d x[token(p),d] * up_a[e,r,d]
// grid (32 mtiles, E) x 256
// ============================================================
__global__ void k_tup(const float* __restrict__ hs, const float* __restrict__ up_a){
    int e = blockIdx.y, mt = blockIdx.x;
    int base = g_off[e], me = g_off[e + 1] - base;
    if (mt * 64 >= me) return;
    int rows = me - mt * 64; if (rows > 64) rows = 64;

    __shared__ float xs[16][68];
    __shared__ float at[16][20];
    __shared__ int   tok[64];

    int t = threadIdx.x;
    if (t < 64){
        int rr = (t < rows) ? t : 0;
        tok[t] = g_perm[base + mt * 64 + rr] / TOPK;
    }
    __syncthreads();

    int row = t & 63, rg = t >> 6;
    float a0 = 0.f, a1 = 0.f, a2 = 0.f, a3 = 0.f;
    const float* A = up_a + (size_t)e * NR * ND;
    int lr = t >> 2, lq = t & 3;
    const float* X = hs + (size_t)tok[lr] * ND + lq * 4;

    for (int d0 = 0; d0 < ND; d0 += 16){
        float4 v = *(const float4*)(X + d0);
        xs[lq*4+0][lr] = v.x; xs[lq*4+1][lr] = v.y; xs[lq*4+2][lr] = v.z; xs[lq*4+3][lr] = v.w;
        if (t < 64){
            float4 w = *(const float4*)(A + (size_t)lr * ND + d0 + lq * 4);
            at[lq*4+0][lr] = w.x; at[lq*4+1][lr] = w.y; at[lq*4+2][lr] = w.z; at[lq*4+3][lr] = w.w;
        }
        __syncthreads();
        #pragma unroll
        for (int kk = 0; kk < 16; kk++){
            float a = xs[kk][row];
            a0 = fmaf(a, at[kk][rg*4+0], a0);
            a1 = fmaf(a, at[kk][rg*4+1], a1);
            a2 = fmaf(a, at[kk][rg*4+2], a2);
            a3 = fmaf(a, at[kk][rg*4+3], a3);
        }
        __syncthreads();
    }
    if (row < rows){
        float* o = g_tup + (size_t)(base + mt * 64 + row) * NR + rg * 4;
        o[0] = a0; o[1] = a1; o[2] = a2; o[3] = a3;
    }
}

// ============================================================
// Kernel: t_dn[p][r] = sum_h act[p,h] * down_a[e,r,h]
// ============================================================
__global__ void k_tdn(const float* __restrict__ down_a){
    int e = blockIdx.y, mt = blockIdx.x;
    int base = g_off[e], me = g_off[e + 1] - base;
    if (mt * 64 >= me) return;
    int rows = me - mt * 64; if (rows > 64) rows = 64;

    __shared__ float xs[16][68];
    __shared__ float at[16][20];

    int t = threadIdx.x;
    int row = t & 63, rg = t >> 6;
    float a0 = 0.f, a1 = 0.f, a2 = 0.f, a3 = 0.f;
    const float* A = down_a + (size_t)e * NR * NH;
    int lr = t >> 2, lq = t & 3;
    int xrr = (lr < rows) ? lr : 0;
    const float* X = g_act + (size_t)(base + mt * 64 + xrr) * NH + lq * 4;

    for (int d0 = 0; d0 < NH; d0 += 16){
        float4 v = *(const float4*)(X + d0);
        xs[lq*4+0][lr] = v.x; xs[lq*4+1][lr] = v.y; xs[lq*4+2][lr] = v.z; xs[lq*4+3][lr] = v.w;
        if (t < 64){
            float4 w = *(const float4*)(A + (size_t)lr * NH + d0 + lq * 4);
            at[lq*4+0][lr] = w.x; at[lq*4+1][lr] = w.y; at[lq*4+2][lr] = w.z; at[lq*4+3][lr] = w.w;
        }
        __syncthreads();
        #pragma unroll
        for (int kk = 0; kk < 16; kk++){
            float a = xs[kk][row];
            a0 = fmaf(a, at[kk][rg*4+0], a0);
            a1 = fmaf(a, at[kk][rg*4+1], a1);
            a2 = fmaf(a, at[kk][rg*4+2], a2);
            a3 = fmaf(a, at[kk][rg*4+3], a3);
        }
        __syncthreads();
    }
    if (row < rows){
        float* o = g_tdn + (size_t)(base + mt * 64 + row) * NR + rg * 4;
        o[0] = a0; o[1] = a1; o[2] = a2; o[3] = a3;
    }
}

// ============================================================
// Kernel: up-proj (both halves) + LoRA + gelu*mul -> g_act
// grid (NH/64, 32, E) x 256; 64x64 tile, 4x4 microtile, f32x2 FMA
// ============================================================
__global__ void __launch_bounds__(256) k_up(
    const float* __restrict__ hs, const float* __restrict__ w_up,
    const float* __restrict__ up_b)
{
    int nt = blockIdx.x, mt = blockIdx.y, e = blockIdx.z;
    int base = g_off[e], me = g_off[e + 1] - base;
    if (mt * 64 >= me) return;
    int rows = me - mt * 64; if (rows > 64) rows = 64;

    __shared__ float xs[16][68], w1s[16][68], w2s[16][68];
    __shared__ int   tok[64];

    int t = threadIdx.x;
    if (t < 64){
        int rr = (t < rows) ? t : 0;
        tok[t] = g_perm[base + mt * 64 + rr] >> 1;  // TOPK=2
    }
    __syncthreads();

    int tx = t & 15, ty = t >> 4;
    u64 acc1[8], acc2[8];
    #pragma unroll
    for (int i = 0; i < 8; i++){ acc1[i] = 0ull; acc2[i] = 0ull; }

    int lr = t >> 2, lq = t & 3;
    const float* X  = hs + (size_t)tok[lr] * ND + lq * 4;
    const float* W1 = w_up + ((size_t)e * 2 * NH + nt * 64 + lr) * ND + lq * 4;
    const float* W2 = w_up + ((size_t)e * 2 * NH + NH + nt * 64 + lr) * ND + lq * 4;

    for (int d0 = 0; d0 < ND; d0 += 16){
        float4 vx = *(const float4*)(X  + d0);
        float4 v1 = *(const float4*)(W1 + d0);
        float4 v2 = *(const float4*)(W2 + d0);
        xs [lq*4+0][lr] = vx.x; xs [lq*4+1][lr] = vx.y; xs [lq*4+2][lr] = vx.z; xs [lq*4+3][lr] = vx.w;
        w1s[lq*4+0][lr] = v1.x; w1s[lq*4+1][lr] = v1.y; w1s[lq*4+2][lr] = v1.z; w1s[lq*4+3][lr] = v1.w;
        w2s[lq*4+0][lr] = v2.x; w2s[lq*4+1][lr] = v2.y; w2s[lq*4+2][lr] = v2.z; w2s[lq*4+3][lr] = v2.w;
        __syncthreads();
        #pragma unroll
        for (int kk = 0; kk < 16; kk++){
            float4 av = *(const float4*)&xs[kk][ty * 4];
            ulonglong2 b1 = *(const ulonglong2*)&w1s[kk][tx * 4];
            ulonglong2 b2 = *(const ulonglong2*)&w2s[kk][tx * 4];
            u64 a0 = pk2(av.x, av.x), a1 = pk2(av.y, av.y);
            u64 a2 = pk2(av.z, av.z), a3 = pk2(av.w, av.w);
            acc1[0] = f2fma(a0, b1.x, acc1[0]); acc1[1] = f2fma(a0, b1.y, acc1[1]);
            acc1[2] = f2fma(a1, b1.x, acc1[2]); acc1[3] = f2fma(a1, b1.y, acc1[3]);
            acc1[4] = f2fma(a2, b1.x, acc1[4]); acc1[5] = f2fma(a2, b1.y, acc1[5]);
            acc1[6] = f2fma(a3, b1.x, acc1[6]); acc1[7] = f2fma(a3, b1.y, acc1[7]);
            acc2[0] = f2fma(a0, b2.x, acc2[0]); acc2[1] = f2fma(a0, b2.y, acc2[1]);
            acc2[2] = f2fma(a1, b2.x, acc2[2]); acc2[3] = f2fma(a1, b2.y, acc2[3]);
            acc2[4] = f2fma(a2, b2.x, acc2[4]); acc2[5] = f2fma(a2, b2.y, acc2[5]);
            acc2[6] = f2fma(a3, b2.x, acc2[6]); acc2[7] = f2fma(a3, b2.y, acc2[7]);
        }
        __syncthreads();
    }

    // ---- epilogue: LoRA-B + exact-erf gelu * mul ----
    __shared__ float ts[64][17], ub1[64][17], ub2[64][17];
    {
        int rr = (lr < rows) ? lr : 0;
        float4 tv  = *(const float4*)(g_tup + (size_t)(base + mt * 64 + rr) * NR + lq * 4);
        ts [lr][lq*4+0] = tv.x;  ts [lr][lq*4+1] = tv.y;  ts [lr][lq*4+2] = tv.z;  ts [lr][lq*4+3] = tv.w;
        float4 b1v = *(const float4*)(up_b + ((size_t)e * 2 * NH + nt * 64 + lr) * NR + lq * 4);
        ub1[lr][lq*4+0] = b1v.x; ub1[lr][lq*4+1] = b1v.y; ub1[lr][lq*4+2] = b1v.z; ub1[lr][lq*4+3] = b1v.w;
        float4 b2v = *(const float4*)(up_b + ((size_t)e * 2 * NH + NH + nt * 64 + lr) * NR + lq * 4);
        ub2[lr][lq*4+0] = b2v.x; ub2[lr][lq*4+1] = b2v.y; ub2[lr][lq*4+2] = b2v.z; ub2[lr][lq*4+3] = b2v.w;
    }
    __syncthreads();

    #pragma unroll
    for (int i = 0; i < 4; i++){
        int row = ty * 4 + i;
        float u1[4], u2[4];
        upk2(acc1[i*2+0], u1[0], u1[1]); upk2(acc1[i*2+1], u1[2], u1[3]);
        upk2(acc2[i*2+0], u2[0], u2[1]); upk2(acc2[i*2+1], u2[2], u2[3]);
        float ov[4];
        #pragma unroll
        for (int j = 0; j < 4; j++){
            float l1 = 0.f, l2 = 0.f;
            #pragma unroll
            for (int r = 0; r < NR; r++){
                float tv = ts[row][r];
                l1 = fmaf(tv, ub1[tx*4+j][r], l1);
                l2 = fmaf(tv, ub2[tx*4+j][r], l2);
            }
            float uu1 = u1[j] + LSCALE * l1;
            float uu2 = u2[j] + LSCALE * l2;
            float g = 0.5f * uu1 * (1.f + erff(uu1 * 0.70710678118654752440f));
            ov[j] = g * uu2;
        }
        if (row < rows){
            float4 st = { ov[0], ov[1], ov[2], ov[3] };
            *(float4*)(g_act + (size_t)(base + mt * 64 + row) * NH + nt * 64 + tx * 4) = st;
        }
    }
}

// ============================================================
// Kernel: down-proj + LoRA + routed weight, atomicAdd into out
// grid (ND/64, 32, E) x 256
// ============================================================
__global__ void __launch_bounds__(256) k_down(
    const float* __restrict__ w_down, const float* __restrict__ down_b,
    const float* __restrict__ topw, float* __restrict__ out)
{
    int nt = blockIdx.x, mt = blockIdx.y, e = blockIdx.z;
    int base = g_off[e], me = g_off[e + 1] - base;
    if (mt * 64 >= me) return;
    int rows = me - mt * 64; if (rows > 64) rows = 64;

    __shared__ float xs[16][68], ws[16][68];
    __shared__ float wgt[64];
    __shared__ int   tokn[64];

    int t = threadIdx.x;
    if (t < 64){
        int rr = (t < rows) ? t : 0;
        int slot = g_perm[base + mt * 64 + rr];
        wgt[t]  = topw[slot];
        tokn[t] = slot >> 1;
    }

    int tx = t & 15, ty = t >> 4;
    u64 acc[8];
    #pragma unroll
    for (int i = 0; i < 8; i++) acc[i] = 0ull;

    int lr = t >> 2, lq = t & 3;
    int xrr = (lr < rows) ? lr : 0;
    const float* X = g_act + (size_t)(base + mt * 64 + xrr) * NH + lq * 4;
    const float* W = w_down + ((size_t)e * ND + nt * 64 + lr) * NH + lq * 4;

    for (int d0 = 0; d0 < NH; d0 += 16){
        float4 vx = *(const float4*)(X + d0);
        float4 vw = *(const float4*)(W + d0);
        xs[lq*4+0][lr] = vx.x; xs[lq*4+1][lr] = vx.y; xs[lq*4+2][lr] = vx.z; xs[lq*4+3][lr] = vx.w;
        ws[lq*4+0][lr] = vw.x; ws[lq*4+1][lr] = vw.y; ws[lq*4+2][lr] = vw.z; ws[lq*4+3][lr] = vw.w;
        __syncthreads();
        #pragma unroll
        for (int kk = 0; kk < 16; kk++){
            float4 av = *(const float4*)&xs[kk][ty * 4];
            ulonglong2 b = *(const ulonglong2*)&ws[kk][tx * 4];
            u64 a0 = pk2(av.x, av.x), a1 = pk2(av.y, av.y);
            u64 a2 = pk2(av.z, av.z), a3 = pk2(av.w, av.w);
            acc[0] = f2fma(a0, b.x, acc[0]); acc[1] = f2fma(a0, b.y, acc[1]);
            acc[2] = f2fma(a1, b.x, acc[2]); acc[3] = f2fma(a1, b.y, acc[3]);
            acc[4] = f2fma(a2, b.x, acc[4]); acc[5] = f2fma(a2, b.y, acc[5]);
            acc[6] = f2fma(a3, b.x, acc[6]); acc[7] = f2fma(a3, b.y, acc[7]);
        }
        __syncthreads();
    }

    // ---- epilogue: LoRA-B + routed weight + atomic accumulate ----
    __shared__ float ts[64][17], db[64][17];
    {
        int rr = (lr < rows) ? lr : 0;
        float4 tv = *(const float4*)(g_tdn + (size_t)(base + mt * 64 + rr) * NR + lq * 4);
        ts[lr][lq*4+0] = tv.x; ts[lr][lq*4+1] = tv.y; ts[lr][lq*4+2] = tv.z; ts[lr][lq*4+3] = tv.w;
        float4 bv = *(const float4*)(down_b + ((size_t)e * ND + nt * 64 + lr) * NR + lq * 4);
        db[lr][lq*4+0] = bv.x; db[lr][lq*4+1] = bv.y; db[lr][lq*4+2] = bv.z; db[lr][lq*4+3] = bv.w;
    }
    __syncthreads();

    #pragma unroll
    for (int i = 0; i < 4; i++){
        int row = ty * 4 + i;
        float a0, a1, a2, a3;
        upk2(acc[i*2+0], a0, a1); upk2(acc[i*2+1], a2, a3);
        float av4[4] = { a0, a1, a2, a3 };
        if (row < rows){
            float w = wgt[row];
            float* obase = out + (size_t)tokn[row] * ND + nt * 64 + tx * 4;
            #pragma unroll
            for (int j = 0; j < 4; j++){
                float l = 0.f;
                #pragma unroll
                for (int r = 0; r < NR; r++) l = fmaf(ts[row][r], db[tx*4+j][r], l);
                atomicAdd(obase + j, (av4[j] + LSCALE * l) * w);
            }
        }
    }
}

// ============================================================
// Launch
// ============================================================
extern "C" void kernel_launch(void* const* d_in, const int* in_sizes, int n_in,
                              void* d_out, int out_size)
{
    (void)in_sizes; (void)n_in; (void)out_size;
    const float* hs   = (const float*)d_in[0];
    const float* topw = (const float*)d_in[1];
    const int*   ids  = (const int*)  d_in[2];
    const float* w_up = (const float*)d_in[3];
    const float* w_dn = (const float*)d_in[4];
    const float* up_a = (const float*)d_in[5];
    const float* up_b = (const float*)d_in[6];
    const float* dn_a = (const float*)d_in[7];
    const float* dn_b = (const float*)d_in[8];
    float* out = (float*)d_out;

    k_zero<<<(N_TOK * ND / 4 + 255) / 256, 256>>>(out);
    k_sort<<<1, 256>>>(ids);
    k_tup <<<dim3(32, NE), 256>>>(hs, up_a);
    k_up  <<<dim3(NH / 64, 32, NE), 256>>>(hs, w_up, up_b);
    k_tdn <<<dim3(32, NE), 256>>>(dn_a);
    k_down<<<dim3(ND / 64, 32, NE), 256>>>(w_dn, dn_b, topw, out);
}

// round 17
// speedup vs baseline: 1.0160x; 1.0160x over previous
#include <cuda_runtime.h>
#include <math.h>

#define N_TOK 1024
#define TOPK  2
#define NE    16
#define NH    1024
#define ND    2048
#define NR    16
#define NS    (N_TOK*TOPK)
#define LSCALE 0.25f
#define KT    32

typedef unsigned long long u64;

// ---- packed f32x2 helpers (sm_100+ PTX; FFMA2 is PTX-only per SASS_QUICKREF) ----
__device__ __forceinline__ u64 pk2(float x, float y){
    u64 r; asm("mov.b64 %0,{%1,%2};" : "=l"(r) : "f"(x), "f"(y)); return r;
}
__device__ __forceinline__ void upk2(u64 v, float& x, float& y){
    asm("mov.b64 {%0,%1},%2;" : "=f"(x), "=f"(y) : "l"(v));
}
__device__ __forceinline__ u64 f2fma(u64 a, u64 b, u64 c){
    u64 d; asm("fma.rn.f32x2 %0,%1,%2,%3;" : "=l"(d) : "l"(a), "l"(b), "l"(c)); return d;
}

// ---- scratch (static device globals: allocation-free) ----
__device__ int   g_perm[NS];
__device__ int   g_off[NE + 1];
__device__ float g_tup[NS * NR];
__device__ float g_tdn[NS * NR];
__device__ float g_act[(size_t)NS * NH];   // 8 MB

// ---- shared memory layouts ----
struct MMTiles {                 // main-loop staging (K-major, swizzled rows)
    float xs[KT][68];
    float w[2][KT][68];
};
struct EPUp {                    // k_up epilogue
    float ts[64][17];
    float ub[2][64][17];
    float u2[64][68];
};
struct EPDn {                    // k_down epilogue
    float ts[64][17];
    float db[2][64][17];
};

// ============================================================
// Kernel: zero output (harness poisons d_out)
// ============================================================
__global__ void k_zero(float* __restrict__ out){
    int i = blockIdx.x * blockDim.x + threadIdx.x;
    float4 z = {0.f, 0.f, 0.f, 0.f};
    if (i < (N_TOK * ND) / 4) ((float4*)out)[i] = z;
}

// ============================================================
// Kernel: counting sort of slots by expert (1 block)
// ============================================================
__global__ void k_sort(const int* __restrict__ ids){
    __shared__ int cnt[NE], cur[NE];
    int t = threadIdx.x;
    if (t < NE) cnt[t] = 0;
    __syncthreads();
    for (int s = t; s < NS; s += blockDim.x) atomicAdd(&cnt[ids[s]], 1);
    __syncthreads();
    if (t == 0){
        int acc = 0;
        for (int e = 0; e < NE; e++){ g_off[e] = acc; cur[e] = acc; acc += cnt[e]; }
        g_off[NE] = acc;
    }
    __syncthreads();
    for (int s = t; s < NS; s += blockDim.x){
        int e = ids[s];
        int p = atomicAdd(&cur[e], 1);
        g_perm[p] = s;
    }
}

// ============================================================
// Kernel: t_up[p][r] = sum_d x[token(p),d] * up_a[e,r,d]
// ============================================================
__global__ void k_tup(const float* __restrict__ hs, const float* __restrict__ up_a){
    int e = blockIdx.y, mt = blockIdx.x;
    int base = g_off[e], me = g_off[e + 1] - base;
    if (mt * 64 >= me) return;
    int rows = me - mt * 64; if (rows > 64) rows = 64;

    __shared__ float xs[16][68];
    __shared__ float at[16][20];
    __shared__ int   tok[64];

    int t = threadIdx.x;
    if (t < 64){
        int rr = (t < rows) ? t : 0;
        tok[t] = g_perm[base + mt * 64 + rr] / TOPK;
    }
    __syncthreads();

    int row = t & 63, rg = t >> 6;
    float a0 = 0.f, a1 = 0.f, a2 = 0.f, a3 = 0.f;
    const float* A = up_a + (size_t)e * NR * ND;
    int lr = t >> 2, lq = t & 3;
    const float* X = hs + (size_t)tok[lr] * ND + lq * 4;

    for (int d0 = 0; d0 < ND; d0 += 16){
        float4 v = *(const float4*)(X + d0);
        xs[lq*4+0][lr] = v.x; xs[lq*4+1][lr] = v.y; xs[lq*4+2][lr] = v.z; xs[lq*4+3][lr] = v.w;
        if (t < 64){
            float4 w = *(const float4*)(A + (size_t)lr * ND + d0 + lq * 4);
            at[lq*4+0][lr] = w.x; at[lq*4+1][lr] = w.y; at[lq*4+2][lr] = w.z; at[lq*4+3][lr] = w.w;
        }
        __syncthreads();
        #pragma unroll
        for (int kk = 0; kk < 16; kk++){
            float a = xs[kk][row];
            a0 = fmaf(a, at[kk][rg*4+0], a0);
            a1 = fmaf(a, at[kk][rg*4+1], a1);
            a2 = fmaf(a, at[kk][rg*4+2], a2);
            a3 = fmaf(a, at[kk][rg*4+3], a3);
        }
        __syncthreads();
    }
    if (row < rows){
        float* o = g_tup + (size_t)(base + mt * 64 + row) * NR + rg * 4;
        o[0] = a0; o[1] = a1; o[2] = a2; o[3] = a3;
    }
}

// ============================================================
// Kernel: t_dn[p][r] = sum_h act[p,h] * down_a[e,r,h]
// ============================================================
__global__ void k_tdn(const float* __restrict__ down_a){
    int e = blockIdx.y, mt = blockIdx.x;
    int base = g_off[e], me = g_off[e + 1] - base;
    if (mt * 64 >= me) return;
    int rows = me - mt * 64; if (rows > 64) rows = 64;

    __shared__ float xs[16][68];
    __shared__ float at[16][20];

    int t = threadIdx.x;
    int row = t & 63, rg = t >> 6;
    float a0 = 0.f, a1 = 0.f, a2 = 0.f, a3 = 0.f;
    const float* A = down_a + (size_t)e * NR * NH;
    int lr = t >> 2, lq = t & 3;
    int xrr = (lr < rows) ? lr : 0;
    const float* X = g_act + (size_t)(base + mt * 64 + xrr) * NH + lq * 4;

    for (int d0 = 0; d0 < NH; d0 += 16){
        float4 v = *(const float4*)(X + d0);
        xs[lq*4+0][lr] = v.x; xs[lq*4+1][lr] = v.y; xs[lq*4+2][lr] = v.z; xs[lq*4+3][lr] = v.w;
        if (t < 64){
            float4 w = *(const float4*)(A + (size_t)lr * NH + d0 + lq * 4);
            at[lq*4+0][lr] = w.x; at[lq*4+1][lr] = w.y; at[lq*4+2][lr] = w.z; at[lq*4+3][lr] = w.w;
        }
        __syncthreads();
        #pragma unroll
        for (int kk = 0; kk < 16; kk++){
            float a = xs[kk][row];
            a0 = fmaf(a, at[kk][rg*4+0], a0);
            a1 = fmaf(a, at[kk][rg*4+1], a1);
            a2 = fmaf(a, at[kk][rg*4+2], a2);
            a3 = fmaf(a, at[kk][rg*4+3], a3);
        }
        __syncthreads();
    }
    if (row < rows){
        float* o = g_tdn + (size_t)(base + mt * 64 + row) * NR + rg * 4;
        o[0] = a0; o[1] = a1; o[2] = a2; o[3] = a3;
    }
}

// ============================================================
// k_up: 512 threads. Group wg (0=gate,1=up) computes a 64x64 tile
// of its half against shared X; exchange via smem for gelu*mul.
// Register-prefetched global loads; swizzled conflict-free STS.
// ============================================================
__global__ void __launch_bounds__(512) k_up(
    const float* __restrict__ hs, const float* __restrict__ w_up,
    const float* __restrict__ up_b)
{
    int nt = blockIdx.x, mt = blockIdx.y, e = blockIdx.z;
    int base = g_off[e], me = g_off[e + 1] - base;
    if (mt * 64 >= me) return;
    int rows = me - mt * 64; if (rows > 64) rows = 64;

    __shared__ union { MMTiles mm; EPUp ep; } sm;
    __shared__ int tok[64];

    int t = threadIdx.x;
    if (t < 64){
        int rr = (t < rows) ? t : 0;
        tok[t] = g_perm[base + mt * 64 + rr] >> 1;   // TOPK=2
    }
    __syncthreads();

    int wg = t >> 8, tt = t & 255;
    int tx = tt & 15, ty = tt >> 4;

    // loader indices
    int lrx = t >> 3, lqx = t & 7;    // X tile: 64 rows x 8 float4 (512 threads, 1 each)
    int lrw = tt >> 2, lqw = tt & 3;  // W tile: per-group 64 rows x 8 float4 (256 thr, 2 each)

    const float* X = hs   + (size_t)tok[lrx] * ND + lqx * 4;
    const float* W = w_up + ((size_t)e * 2 * NH + (size_t)wg * NH + nt * 64 + lrw) * ND + lqw * 4;

    float4 rx  = *(const float4*)(X);
    float4 rw0 = *(const float4*)(W);
    float4 rw1 = *(const float4*)(W + 16);

    u64 acc[8];
    #pragma unroll
    for (int i = 0; i < 8; i++) acc[i] = 0ull;

    for (int d0 = 0; d0 < ND; d0 += KT){
        {   // staged stores with row-XOR swizzle (conflict-free)
            int k0 = lqx * 4;
            #pragma unroll
            for (int i = 0; i < 4; i++)
                sm.mm.xs[k0 + i][lrx ^ ((k0 + i) & 28)] = ((float*)&rx)[i];
            int k1 = lqw * 4, k2 = lqw * 4 + 16;
            #pragma unroll
            for (int i = 0; i < 4; i++)
                sm.mm.w[wg][k1 + i][lrw ^ ((k1 + i) & 28)] = ((float*)&rw0)[i];
            #pragma unroll
            for (int i = 0; i < 4; i++)
                sm.mm.w[wg][k2 + i][lrw ^ ((k2 + i) & 28)] = ((float*)&rw1)[i];
        }
        __syncthreads();
        if (d0 + KT < ND){   // prefetch next tile into regs (hidden under compute)
            rx  = *(const float4*)(X + d0 + KT);
            rw0 = *(const float4*)(W + d0 + KT);
            rw1 = *(const float4*)(W + d0 + KT + 16);
        }
        #pragma unroll 8
        for (int kk = 0; kk < KT; kk++){
            float4 av = *(const float4*)&sm.mm.xs[kk][(ty * 4) ^ (kk & 28)];
            ulonglong2 b = *(const ulonglong2*)&sm.mm.w[wg][kk][(tx * 4) ^ (kk & 28)];
            u64 a0 = pk2(av.x, av.x), a1 = pk2(av.y, av.y);
            u64 a2 = pk2(av.z, av.z), a3 = pk2(av.w, av.w);
            acc[0] = f2fma(a0, b.x, acc[0]); acc[1] = f2fma(a0, b.y, acc[1]);
            acc[2] = f2fma(a1, b.x, acc[2]); acc[3] = f2fma(a1, b.y, acc[3]);
            acc[4] = f2fma(a2, b.x, acc[4]); acc[5] = f2fma(a2, b.y, acc[5]);
            acc[6] = f2fma(a3, b.x, acc[6]); acc[7] = f2fma(a3, b.y, acc[7]);
        }
        __syncthreads();
    }

    // ---- epilogue: LoRA-B + exchange + exact-erf gelu * mul ----
    if (t < 256){   // ts: group-0 threads load g_tup tile
        int rr = (lrw < rows) ? lrw : 0;
        float4 tv = *(const float4*)(g_tup + (size_t)(base + mt * 64 + rr) * NR + lqw * 4);
        sm.ep.ts[lrw][lqw*4+0] = tv.x; sm.ep.ts[lrw][lqw*4+1] = tv.y;
        sm.ep.ts[lrw][lqw*4+2] = tv.z; sm.ep.ts[lrw][lqw*4+3] = tv.w;
    }
    {   // ub[wg]: each group loads its half of up_b
        float4 bv = *(const float4*)(up_b + ((size_t)e * 2 * NH + (size_t)wg * NH + nt * 64 + lrw) * NR + lqw * 4);
        sm.ep.ub[wg][lrw][lqw*4+0] = bv.x; sm.ep.ub[wg][lrw][lqw*4+1] = bv.y;
        sm.ep.ub[wg][lrw][lqw*4+2] = bv.z; sm.ep.ub[wg][lrw][lqw*4+3] = bv.w;
    }
    __syncthreads();

    float uu[4][4];
    #pragma unroll
    for (int i = 0; i < 4; i++){
        int row = ty * 4 + i;
        float u[4];
        upk2(acc[i*2+0], u[0], u[1]); upk2(acc[i*2+1], u[2], u[3]);
        #pragma unroll
        for (int j = 0; j < 4; j++){
            float l = 0.f;
            #pragma unroll
            for (int r = 0; r < NR; r++)
                l = fmaf(sm.ep.ts[row][r], sm.ep.ub[wg][tx*4+j][r], l);
            uu[i][j] = u[j] + LSCALE * l;
        }
    }
    if (wg == 1){
        #pragma unroll
        for (int i = 0; i < 4; i++){
            float4 st = { uu[i][0], uu[i][1], uu[i][2], uu[i][3] };
            *(float4*)&sm.ep.u2[ty*4+i][tx*4] = st;
        }
    }
    __syncthreads();
    if (wg == 0){
        #pragma unroll
        for (int i = 0; i < 4; i++){
            int row = ty * 4 + i;
            if (row < rows){
                float4 u2v = *(const float4*)&sm.ep.u2[row][tx*4];
                float ov[4]; float* u2p = (float*)&u2v;
                #pragma unroll
                for (int j = 0; j < 4; j++){
                    float g = 0.5f * uu[i][j] * (1.f + erff(uu[i][j] * 0.70710678118654752440f));
                    ov[j] = g * u2p[j];
                }
                float4 st = { ov[0], ov[1], ov[2], ov[3] };
                *(float4*)(g_act + (size_t)(base + mt * 64 + row) * NH + nt * 64 + tx * 4) = st;
            }
        }
    }
}

// ============================================================
// k_down: 512 threads, tile 64M x 128N (group wg owns 64 cols).
// Same prefetch + swizzle structure; LoRA + routed weight + atomics.
// ============================================================
__global__ void __launch_bounds__(512) k_down(
    const float* __restrict__ w_down, const float* __restrict__ down_b,
    const float* __restrict__ topw, float* __restrict__ out)
{
    int nt = blockIdx.x, mt = blockIdx.y, e = blockIdx.z;
    int base = g_off[e], me = g_off[e + 1] - base;
    if (mt * 64 >= me) return;
    int rows = me - mt * 64; if (rows > 64) rows = 64;

    __shared__ union { MMTiles mm; EPDn ep; } sm;
    __shared__ float wgt[64];
    __shared__ int   tokn[64];

    int t = threadIdx.x;
    if (t < 64){
        int rr = (t < rows) ? t : 0;
        int slot = g_perm[base + mt * 64 + rr];
        wgt[t]  = topw[slot];
        tokn[t] = slot >> 1;
    }
    __syncthreads();

    int wg = t >> 8, tt = t & 255;
    int tx = tt & 15, ty = tt >> 4;

    int lrx = t >> 3, lqx = t & 7;
    int lrw = tt >> 2, lqw = tt & 3;

    int xrr = (lrx < rows) ? lrx : 0;
    const float* X = g_act  + (size_t)(base + mt * 64 + xrr) * NH + lqx * 4;
    const float* W = w_down + ((size_t)e * ND + nt * 128 + wg * 64 + lrw) * NH + lqw * 4;

    float4 rx  = *(const float4*)(X);
    float4 rw0 = *(const float4*)(W);
    float4 rw1 = *(const float4*)(W + 16);

    u64 acc[8];
    #pragma unroll
    for (int i = 0; i < 8; i++) acc[i] = 0ull;

    for (int d0 = 0; d0 < NH; d0 += KT){
        {
            int k0 = lqx * 4;
            #pragma unroll
            for (int i = 0; i < 4; i++)
                sm.mm.xs[k0 + i][lrx ^ ((k0 + i) & 28)] = ((float*)&rx)[i];
            int k1 = lqw * 4, k2 = lqw * 4 + 16;
            #pragma unroll
            for (int i = 0; i < 4; i++)
                sm.mm.w[wg][k1 + i][lrw ^ ((k1 + i) & 28)] = ((float*)&rw0)[i];
            #pragma unroll
            for (int i = 0; i < 4; i++)
                sm.mm.w[wg][k2 + i][lrw ^ ((k2 + i) & 28)] = ((float*)&rw1)[i];
        }
        __syncthreads();
        if (d0 + KT < NH){
            rx  = *(const float4*)(X + d0 + KT);
            rw0 = *(const float4*)(W + d0 + KT);
            rw1 = *(const float4*)(W + d0 + KT + 16);
        }
        #pragma unroll 8
        for (int kk = 0; kk < KT; kk++){
            float4 av = *(const float4*)&sm.mm.xs[kk][(ty * 4) ^ (kk & 28)];
            ulonglong2 b = *(const ulonglong2*)&sm.mm.w[wg][kk][(tx * 4) ^ (kk & 28)];
            u64 a0 = pk2(av.x, av.x), a1 = pk2(av.y, av.y);
            u64 a2 = pk2(av.z, av.z), a3 = pk2(av.w, av.w);
            acc[0] = f2fma(a0, b.x, acc[0]); acc[1] = f2fma(a0, b.y, acc[1]);
            acc[2] = f2fma(a1, b.x, acc[2]); acc[3] = f2fma(a1, b.y, acc[3]);
            acc[4] = f2fma(a2, b.x, acc[4]); acc[5] = f2fma(a2, b.y, acc[5]);
            acc[6] = f2fma(a3, b.x, acc[6]); acc[7] = f2fma(a3, b.y, acc[7]);
        }
        __syncthreads();
    }

    // ---- epilogue: LoRA-B + routed weight + atomic accumulate ----
    if (t < 256){
        int rr = (lrw < rows) ? lrw : 0;
        float4 tv = *(const float4*)(g_tdn + (size_t)(base + mt * 64 + rr) * NR + lqw * 4);
        sm.ep.ts[lrw][lqw*4+0] = tv.x; sm.ep.ts[lrw][lqw*4+1] = tv.y;
        sm.ep.ts[lrw][lqw*4+2] = tv.z; sm.ep.ts[lrw][lqw*4+3] = tv.w;
    }
    {
        float4 bv = *(const float4*)(down_b + ((size_t)e * ND + nt * 128 + wg * 64 + lrw) * NR + lqw * 4);
        sm.ep.db[wg][lrw][lqw*4+0] = bv.x; sm.ep.db[wg][lrw][lqw*4+1] = bv.y;
        sm.ep.db[wg][lrw][lqw*4+2] = bv.z; sm.ep.db[wg][lrw][lqw*4+3] = bv.w;
    }
    __syncthreads();

    #pragma unroll
    for (int i = 0; i < 4; i++){
        int row = ty * 4 + i;
        float a[4];
        upk2(acc[i*2+0], a[0], a[1]); upk2(acc[i*2+1], a[2], a[3]);
        if (row < rows){
            float w = wgt[row];
            float* obase = out + (size_t)tokn[row] * ND + nt * 128 + wg * 64 + tx * 4;
            #pragma unroll
            for (int j = 0; j < 4; j++){
                float l = 0.f;
                #pragma unroll
                for (int r = 0; r < NR; r++)
                    l = fmaf(sm.ep.ts[row][r], sm.ep.db[wg][tx*4+j][r], l);
                atomicAdd(obase + j, (a[j] + LSCALE * l) * w);
            }
        }
    }
}

// ============================================================
// Launch
// ============================================================
extern "C" void kernel_launch(void* const* d_in, const int* in_sizes, int n_in,
                              void* d_out, int out_size)
{
    (void)in_sizes; (void)n_in; (void)out_size;
    const float* hs   = (const float*)d_in[0];
    const float* topw = (const float*)d_in[1];
    const int*   ids  = (const int*)  d_in[2];
    const float* w_up = (const float*)d_in[3];
    const float* w_dn = (const float*)d_in[4];
    const float* up_a = (const float*)d_in[5];
    const float* up_b = (const float*)d_in[6];
    const float* dn_a = (const float*)d_in[7];
    const float* dn_b = (const float*)d_in[8];
    float* out = (float*)d_out;

    k_zero<<<(N_TOK * ND / 4 + 255) / 256, 256>>>(out);
    k_sort<<<1, 256>>>(ids);
    k_tup <<<dim3(32, NE), 256>>>(hs, up_a);
    k_up  <<<dim3(NH / 64, 32, NE), 512>>>(hs, w_up, up_b);
    k_tdn <<<dim3(32, NE), 256>>>(dn_a);
    k_down<<<dim3(ND / 128, 32, NE), 512>>>(w_dn, dn_b, topw, out);
}